// round 1
// baseline (speedup 1.0000x reference)
#include <cuda_runtime.h>

#define BATCH 4
#define SEQ   2048
#define DIM   1024

// ---- scratch (alloc-free rule: __device__ globals) ----
__device__ float g_qkv[(long)BATCH * SEQ * 3 * DIM];   // [8192][3072]
__device__ float g_scores[(long)BATCH * SEQ * SEQ];    // [4][2048][2048]
__device__ float g_attn_out[(long)BATCH * SEQ * DIM];  // [8192][1024]

constexpr int BM = 128, BN = 128, BK = 16;

// MODE: 0 = +bias, 1 = *scale then mask->1e-10, 2 = plain
// BT:   true  -> B is [N,K] row-major (read B[n*ldb+k])
//       false -> B is [K,N] row-major (read B[k*ldb+n])
template <int MODE, bool BT>
__global__ __launch_bounds__(256) void gemm_kernel(
    const float* __restrict__ A, int lda,
    const float* __restrict__ B, int ldb,
    float* __restrict__ C, int ldc,
    int K,
    const float* __restrict__ bias,
    const int* __restrict__ mask, float scale,
    long strideA, long strideB, long strideC, long strideMask)
{
    __shared__ float As[BK][BM];
    __shared__ float Bs[BK][BN];

    const int bz = blockIdx.z;
    A += (long)bz * strideA;
    B += (long)bz * strideB;
    C += (long)bz * strideC;
    if (MODE == 1) mask += (long)bz * strideMask;

    const int m0 = blockIdx.y * BM;
    const int n0 = blockIdx.x * BN;
    const int tid = threadIdx.x;
    const int tx = tid & 15;        // 0..15 -> N
    const int ty = tid >> 4;        // 0..15 -> M

    float acc[8][8] = {};

    for (int k0 = 0; k0 < K; k0 += BK) {
        // stage A: As[k][m] = A[(m0+m)*lda + k0+k]   (2048 floats = 512 float4)
        #pragma unroll
        for (int it = 0; it < 2; it++) {
            int idx4 = tid + it * 256;          // [0,512)
            int m  = idx4 >> 2;
            int kq = (idx4 & 3) * 4;
            float4 v = *(const float4*)&A[(long)(m0 + m) * lda + k0 + kq];
            As[kq + 0][m] = v.x;
            As[kq + 1][m] = v.y;
            As[kq + 2][m] = v.z;
            As[kq + 3][m] = v.w;
        }
        // stage B
        if (BT) {
            #pragma unroll
            for (int it = 0; it < 2; it++) {
                int idx4 = tid + it * 256;
                int n  = idx4 >> 2;
                int kq = (idx4 & 3) * 4;
                float4 v = *(const float4*)&B[(long)(n0 + n) * ldb + k0 + kq];
                Bs[kq + 0][n] = v.x;
                Bs[kq + 1][n] = v.y;
                Bs[kq + 2][n] = v.z;
                Bs[kq + 3][n] = v.w;
            }
        } else {
            #pragma unroll
            for (int it = 0; it < 2; it++) {
                int idx4 = tid + it * 256;
                int k  = idx4 >> 5;             // /32  (32 float4 per k-row)
                int nq = (idx4 & 31) * 4;
                float4 v = *(const float4*)&B[(long)(k0 + k) * ldb + n0 + nq];
                *(float4*)&Bs[k][nq] = v;
            }
        }
        __syncthreads();

        #pragma unroll
        for (int k = 0; k < BK; k++) {
            float a[8], b[8];
            #pragma unroll
            for (int i = 0; i < 8; i++) a[i] = As[k][ty * 8 + i];
            #pragma unroll
            for (int j = 0; j < 8; j++) b[j] = Bs[k][tx * 8 + j];
            #pragma unroll
            for (int i = 0; i < 8; i++)
                #pragma unroll
                for (int j = 0; j < 8; j++)
                    acc[i][j] += a[i] * b[j];
        }
        __syncthreads();
    }

    // epilogue
    #pragma unroll
    for (int i = 0; i < 8; i++) {
        const int row = m0 + ty * 8 + i;
        #pragma unroll
        for (int j = 0; j < 8; j += 4) {
            const int col = n0 + tx * 8 + j;
            float4 v;
            float* pv = &v.x;
            #pragma unroll
            for (int q = 0; q < 4; q++) {
                float val = acc[i][j + q];
                if (MODE == 0) val += bias[col + q];
                if (MODE == 1) {
                    val *= scale;
                    if (mask[(long)row * ldc + col + q] == 0) val = 1e-10f;
                }
                pv[q] = val;
            }
            *(float4*)&C[(long)row * ldc + col] = v;
        }
    }
}

// Row-wise softmax over SEQ=2048 elements, in place. One block per row.
__global__ __launch_bounds__(256) void softmax_kernel(float* __restrict__ s)
{
    const long row = blockIdx.x;
    float* p = s + row * SEQ;
    const int tid  = threadIdx.x;
    const int lane = tid & 31;
    const int warp = tid >> 5;

    __shared__ float redm[8];
    __shared__ float reds[8];

    float v[8];
    float m = -1e30f;
    #pragma unroll
    for (int i = 0; i < 8; i++) {
        v[i] = p[tid + i * 256];
        m = fmaxf(m, v[i]);
    }
    #pragma unroll
    for (int o = 16; o > 0; o >>= 1) m = fmaxf(m, __shfl_xor_sync(0xffffffffu, m, o));
    if (lane == 0) redm[warp] = m;
    __syncthreads();
    float M = redm[0];
    #pragma unroll
    for (int i = 1; i < 8; i++) M = fmaxf(M, redm[i]);

    float sum = 0.f;
    #pragma unroll
    for (int i = 0; i < 8; i++) {
        v[i] = expf(v[i] - M);
        sum += v[i];
    }
    #pragma unroll
    for (int o = 16; o > 0; o >>= 1) sum += __shfl_xor_sync(0xffffffffu, sum, o);
    if (lane == 0) reds[warp] = sum;
    __syncthreads();
    float total = 0.f;
    #pragma unroll
    for (int i = 0; i < 8; i++) total += reds[i];

    const float inv = 1.0f / total;
    #pragma unroll
    for (int i = 0; i < 8; i++) p[tid + i * 256] = v[i] * inv;
}

extern "C" void kernel_launch(void* const* d_in, const int* in_sizes, int n_in,
                              void* d_out, int out_size)
{
    const float* x    = (const float*)d_in[0];
    const int*   mask = (const int*)  d_in[1];
    const float* Wqkv = (const float*)d_in[2];
    const float* bqkv = (const float*)d_in[3];
    const float* Wout = (const float*)d_in[4];
    const float* bout = (const float*)d_in[5];
    float* out = (float*)d_out;

    float* qkv;      cudaGetSymbolAddress((void**)&qkv,      g_qkv);
    float* scores;   cudaGetSymbolAddress((void**)&scores,   g_scores);
    float* attn_out; cudaGetSymbolAddress((void**)&attn_out, g_attn_out);

    const int M  = BATCH * SEQ;          // 8192
    const float scale = 0.03125f;        // 1/sqrt(1024)

    // 1) qkv = x @ Wqkv + bqkv        [8192,1024]x[1024,3072]
    gemm_kernel<0, false><<<dim3(3 * DIM / BN, M / BM, 1), 256>>>(
        x, DIM, Wqkv, 3 * DIM, qkv, 3 * DIM, DIM,
        bqkv, nullptr, 0.f, 0, 0, 0, 0);

    // 2) scores = Q @ K^T * scale, masked -> 1e-10   (per batch)
    gemm_kernel<1, true><<<dim3(SEQ / BN, SEQ / BM, BATCH), 256>>>(
        qkv /*Q*/, 3 * DIM, qkv + DIM /*K*/, 3 * DIM, scores, SEQ, DIM,
        nullptr, mask, scale,
        (long)SEQ * 3 * DIM, (long)SEQ * 3 * DIM, (long)SEQ * SEQ, (long)SEQ * SEQ);

    // 3) softmax rows (in place)
    softmax_kernel<<<BATCH * SEQ, 256>>>(scores);

    // 4) attn_out = attn @ V          (per batch) [2048,2048]x[2048,1024]
    gemm_kernel<2, false><<<dim3(DIM / BN, SEQ / BM, BATCH), 256>>>(
        scores, SEQ, qkv + 2 * DIM /*V*/, 3 * DIM, attn_out, DIM, SEQ,
        nullptr, nullptr, 0.f,
        (long)SEQ * SEQ, (long)SEQ * 3 * DIM, (long)SEQ * DIM, 0);

    // 5) out = attn_out @ Wout + bout [8192,1024]x[1024,1024]
    gemm_kernel<0, false><<<dim3(DIM / BN, M / BM, 1), 256>>>(
        attn_out, DIM, Wout, DIM, out, DIM, DIM,
        bout, nullptr, 0.f, 0, 0, 0, 0);
}

// round 3
// speedup vs baseline: 3.2727x; 3.2727x over previous
#include <cuda_runtime.h>
#include <cstdint>

#define BATCH 4
#define SEQ   2048
#define DIM   1024

// ---- scratch (alloc-free rule: __device__ globals) ----
__device__ float g_qkv   [(size_t)BATCH * SEQ * 3 * DIM];   // [8192][3072]
__device__ float g_scores[(size_t)BATCH * SEQ * SEQ];       // [4][2048][2048]
__device__ float g_attn  [(size_t)BATCH * SEQ * DIM];       // [8192][1024]
__device__ float g_wqkvT [(size_t)3 * DIM * DIM];           // [3072][1024]
__device__ float g_woutT [(size_t)DIM * DIM];               // [1024][1024]
__device__ float g_vT    [(size_t)BATCH * DIM * SEQ];       // [4][1024][2048]

// =========================== mma helpers (baseline PTX) ===========================
__device__ __forceinline__ uint32_t f2tf32(float x) {
    uint32_t r;
    asm("cvt.rna.tf32.f32 %0, %1;" : "=r"(r) : "f"(x));
    return r;
}

__device__ __forceinline__ void mma_tf32(float* d, const uint32_t* a, const uint32_t* b) {
    asm volatile(
        "mma.sync.aligned.m16n8k8.row.col.f32.tf32.tf32.f32 "
        "{%0,%1,%2,%3}, {%4,%5,%6,%7}, {%8,%9}, {%0,%1,%2,%3};"
        : "+f"(d[0]), "+f"(d[1]), "+f"(d[2]), "+f"(d[3])
        : "r"(a[0]), "r"(a[1]), "r"(a[2]), "r"(a[3]), "r"(b[0]), "r"(b[1]));
}

// =========================== GEMM (mma.sync tf32) ===========================
// C[M,N] = A[M,K] * B[N,K]^T.  A row-major [M,K], B row-major [N,K].
// Block tile 128x256, BK=32. 256 threads = 8 warps (2 m x 4 n), warp tile 64x64.
// MODE 0: +bias[n]   MODE 1: *scale then mask==0 -> 1e-10   MODE 2: plain

constexpr int BM = 128, BN = 256, BK = 32;
constexpr int LDS_ROW = BK + 4;                        // 36 floats, 144 B
constexpr int A_FLOATS = BM * LDS_ROW;                 // 4608
constexpr int B_FLOATS = BN * LDS_ROW;                 // 9216
constexpr int STAGE_FLOATS = A_FLOATS + B_FLOATS;      // 13824
constexpr int SMEM_BYTES = 2 * STAGE_FLOATS * 4;       // 110592

template <int MODE>
__global__ __launch_bounds__(256) void gemm_mma(
    const float* __restrict__ A, int lda,
    const float* __restrict__ B, int ldb,
    float* __restrict__ C, int ldc, int K,
    const float* __restrict__ bias,
    const int* __restrict__ mask, float scale,
    long sA, long sB, long sC, long sM)
{
    extern __shared__ uint32_t smem[];
    const int tid  = threadIdx.x;
    const int lane = tid & 31;
    const int wid  = tid >> 5;
    const int bz   = blockIdx.z;

    A += (long)bz * sA;
    B += (long)bz * sB;
    C += (long)bz * sC;
    if (MODE == 1) mask += (long)bz * sM;

    const int m0 = blockIdx.y * BM;
    const int n0 = blockIdx.x * BN;

    const int wm = (wid & 1) * 64;     // warp m offset within tile
    const int wn = (wid >> 1) * 64;    // warp n offset within tile
    const int lr = lane >> 2;          // 0..7
    const int lc = lane & 3;           // 0..3

    float acc[4][8][4];
    #pragma unroll
    for (int i = 0; i < 4; i++)
        #pragma unroll
        for (int j = 0; j < 8; j++)
            #pragma unroll
            for (int q = 0; q < 4; q++) acc[i][j][q] = 0.f;

    // per-thread load coords (A: 4 float4, B: 8 float4 per stage)
    const int arow = tid >> 3;             // base row for A (i adds 32)
    const int aq   = (tid & 7) * 4;        // k offset (floats)
    const int brow = tid >> 3;
    const int bq   = (tid & 7) * 4;

    const int NITER = K / BK;

    // ---- preload stage 0 ----
    {
        uint32_t* As = smem;
        uint32_t* Bs = smem + A_FLOATS;
        #pragma unroll
        for (int i = 0; i < 4; i++) {
            const int r = arow + i * 32;
            float4 v = *(const float4*)(A + (size_t)(m0 + r) * lda + aq);
            uint32_t* p = As + r * LDS_ROW + aq;
            p[0] = f2tf32(v.x); p[1] = f2tf32(v.y); p[2] = f2tf32(v.z); p[3] = f2tf32(v.w);
        }
        #pragma unroll
        for (int i = 0; i < 8; i++) {
            const int r = brow + i * 32;
            float4 v = *(const float4*)(B + (size_t)(n0 + r) * ldb + bq);
            uint32_t* p = Bs + r * LDS_ROW + bq;
            p[0] = f2tf32(v.x); p[1] = f2tf32(v.y); p[2] = f2tf32(v.z); p[3] = f2tf32(v.w);
        }
    }
    __syncthreads();

    float4 pa[4], pb[8];

    #pragma unroll 1
    for (int kc = 0; kc < NITER; kc++) {
        const uint32_t* As = smem + (kc & 1) * STAGE_FLOATS;
        const uint32_t* Bs = As + A_FLOATS;

        // prefetch next stage from global
        if (kc + 1 < NITER) {
            const int kb = (kc + 1) * BK;
            #pragma unroll
            for (int i = 0; i < 4; i++)
                pa[i] = *(const float4*)(A + (size_t)(m0 + arow + i * 32) * lda + kb + aq);
            #pragma unroll
            for (int i = 0; i < 8; i++)
                pb[i] = *(const float4*)(B + (size_t)(n0 + brow + i * 32) * ldb + kb + bq);
        }

        // compute: 4 k-steps of 8
        const uint32_t* Abase = As + (wm + lr) * LDS_ROW + lc;
        const uint32_t* Bbase = Bs + (wn + lr) * LDS_ROW + lc;
        #pragma unroll
        for (int kk = 0; kk < BK; kk += 8) {
            uint32_t a[4][4], b[8][2];
            #pragma unroll
            for (int mi = 0; mi < 4; mi++) {
                const uint32_t* p = Abase + mi * 16 * LDS_ROW + kk;
                a[mi][0] = p[0];
                a[mi][1] = p[8 * LDS_ROW];
                a[mi][2] = p[4];
                a[mi][3] = p[8 * LDS_ROW + 4];
            }
            #pragma unroll
            for (int ni = 0; ni < 8; ni++) {
                const uint32_t* p = Bbase + ni * 8 * LDS_ROW + kk;
                b[ni][0] = p[0];
                b[ni][1] = p[4];
            }
            #pragma unroll
            for (int mi = 0; mi < 4; mi++)
                #pragma unroll
                for (int ni = 0; ni < 8; ni++)
                    mma_tf32(acc[mi][ni], a[mi], b[ni]);
        }

        // store next stage to the other buffer
        if (kc + 1 < NITER) {
            uint32_t* As2 = smem + ((kc + 1) & 1) * STAGE_FLOATS;
            uint32_t* Bs2 = As2 + A_FLOATS;
            #pragma unroll
            for (int i = 0; i < 4; i++) {
                uint32_t* p = As2 + (arow + i * 32) * LDS_ROW + aq;
                p[0] = f2tf32(pa[i].x); p[1] = f2tf32(pa[i].y);
                p[2] = f2tf32(pa[i].z); p[3] = f2tf32(pa[i].w);
            }
            #pragma unroll
            for (int i = 0; i < 8; i++) {
                uint32_t* p = Bs2 + (brow + i * 32) * LDS_ROW + bq;
                p[0] = f2tf32(pb[i].x); p[1] = f2tf32(pb[i].y);
                p[2] = f2tf32(pb[i].z); p[3] = f2tf32(pb[i].w);
            }
        }
        __syncthreads();
    }

    // ---- epilogue: fragment writeback (float2 per c-pair) ----
    #pragma unroll
    for (int mi = 0; mi < 4; mi++) {
        #pragma unroll
        for (int half = 0; half < 2; half++) {
            const int row = m0 + wm + mi * 16 + lr + half * 8;
            float* crow = C + (size_t)row * ldc;
            const int* mrow = (MODE == 1) ? (mask + (size_t)row * ldc) : nullptr;
            #pragma unroll
            for (int ni = 0; ni < 8; ni++) {
                const int col = n0 + wn + ni * 8 + lc * 2;
                float v0 = acc[mi][ni][half * 2 + 0];
                float v1 = acc[mi][ni][half * 2 + 1];
                if (MODE == 0) {
                    v0 += bias[col];
                    v1 += bias[col + 1];
                }
                if (MODE == 1) {
                    v0 *= scale; v1 *= scale;
                    const int2 mk = *(const int2*)(mrow + col);
                    if (mk.x == 0) v0 = 1e-10f;
                    if (mk.y == 0) v1 = 1e-10f;
                }
                float2 v; v.x = v0; v.y = v1;
                *(float2*)(crow + col) = v;
            }
        }
    }
}

// =========================== transpose ===========================
__global__ __launch_bounds__(256) void transpose_kernel(
    const float* __restrict__ src, float* __restrict__ dst,
    int srcLd, int dstLd, long sBatch, long dBatch)
{
    __shared__ float t[32][33];
    src += (long)blockIdx.z * sBatch;
    dst += (long)blockIdx.z * dBatch;
    const int c0 = blockIdx.x * 32, r0 = blockIdx.y * 32;
    const int tx = threadIdx.x, ty = threadIdx.y;
    #pragma unroll
    for (int i = 0; i < 32; i += 8)
        t[ty + i][tx] = src[(size_t)(r0 + ty + i) * srcLd + c0 + tx];
    __syncthreads();
    #pragma unroll
    for (int i = 0; i < 32; i += 8)
        dst[(size_t)(c0 + ty + i) * dstLd + r0 + tx] = t[tx][ty + i];
}

// =========================== softmax ===========================
__global__ __launch_bounds__(256) void softmax_kernel(float* __restrict__ s)
{
    const long row = blockIdx.x;
    float* p = s + row * SEQ;
    const int tid  = threadIdx.x;
    const int lane = tid & 31;
    const int warp = tid >> 5;

    __shared__ float redm[8];
    __shared__ float reds[8];

    float v[8];
    float m = -1e30f;
    #pragma unroll
    for (int i = 0; i < 8; i++) {
        v[i] = p[tid + i * 256];
        m = fmaxf(m, v[i]);
    }
    #pragma unroll
    for (int o = 16; o > 0; o >>= 1) m = fmaxf(m, __shfl_xor_sync(0xffffffffu, m, o));
    if (lane == 0) redm[warp] = m;
    __syncthreads();
    float M = redm[0];
    #pragma unroll
    for (int i = 1; i < 8; i++) M = fmaxf(M, redm[i]);

    float sum = 0.f;
    #pragma unroll
    for (int i = 0; i < 8; i++) {
        v[i] = expf(v[i] - M);
        sum += v[i];
    }
    #pragma unroll
    for (int o = 16; o > 0; o >>= 1) sum += __shfl_xor_sync(0xffffffffu, sum, o);
    if (lane == 0) reds[warp] = sum;
    __syncthreads();
    float total = 0.f;
    #pragma unroll
    for (int i = 0; i < 8; i++) total += reds[i];

    const float inv = 1.0f / total;
    #pragma unroll
    for (int i = 0; i < 8; i++) p[tid + i * 256] = v[i] * inv;
}

// =========================== launch ===========================
extern "C" void kernel_launch(void* const* d_in, const int* in_sizes, int n_in,
                              void* d_out, int out_size)
{
    const float* x    = (const float*)d_in[0];
    const int*   mask = (const int*)  d_in[1];
    const float* Wqkv = (const float*)d_in[2];
    const float* bqkv = (const float*)d_in[3];
    const float* Wout = (const float*)d_in[4];
    const float* bout = (const float*)d_in[5];
    float* out = (float*)d_out;

    float* qkv;    cudaGetSymbolAddress((void**)&qkv,    g_qkv);
    float* scores; cudaGetSymbolAddress((void**)&scores, g_scores);
    float* attn;   cudaGetSymbolAddress((void**)&attn,   g_attn);
    float* wqkvT;  cudaGetSymbolAddress((void**)&wqkvT,  g_wqkvT);
    float* woutT;  cudaGetSymbolAddress((void**)&woutT,  g_woutT);
    float* vT;     cudaGetSymbolAddress((void**)&vT,     g_vT);

    cudaFuncSetAttribute(gemm_mma<0>, cudaFuncAttributeMaxDynamicSharedMemorySize, SMEM_BYTES);
    cudaFuncSetAttribute(gemm_mma<1>, cudaFuncAttributeMaxDynamicSharedMemorySize, SMEM_BYTES);
    cudaFuncSetAttribute(gemm_mma<2>, cudaFuncAttributeMaxDynamicSharedMemorySize, SMEM_BYTES);

    const float scale = 0.03125f;  // 1/sqrt(1024)
    const int M = BATCH * SEQ;     // 8192

    // transpose weights: WqkvT [3072][1024], WoutT [1024][1024]
    transpose_kernel<<<dim3(3 * DIM / 32, DIM / 32, 1), dim3(32, 8)>>>(
        Wqkv, wqkvT, 3 * DIM, DIM, 0, 0);
    transpose_kernel<<<dim3(DIM / 32, DIM / 32, 1), dim3(32, 8)>>>(
        Wout, woutT, DIM, DIM, 0, 0);

    // 1) qkv = x @ Wqkv + bqkv
    gemm_mma<0><<<dim3(3 * DIM / BN, M / BM, 1), 256, SMEM_BYTES>>>(
        x, DIM, wqkvT, DIM, qkv, 3 * DIM, DIM,
        bqkv, nullptr, 0.f, 0, 0, 0, 0);

    // transpose V per batch: vT [4][1024][2048]
    transpose_kernel<<<dim3(DIM / 32, SEQ / 32, BATCH), dim3(32, 8)>>>(
        qkv + 2 * DIM, vT, 3 * DIM, SEQ, (long)SEQ * 3 * DIM, (long)DIM * SEQ);

    // 2) scores = Q @ K^T * scale, mask==0 -> 1e-10
    gemm_mma<1><<<dim3(SEQ / BN, SEQ / BM, BATCH), 256, SMEM_BYTES>>>(
        qkv, 3 * DIM, qkv + DIM, 3 * DIM, scores, SEQ, DIM,
        nullptr, mask, scale,
        (long)SEQ * 3 * DIM, (long)SEQ * 3 * DIM, (long)SEQ * SEQ, (long)SEQ * SEQ);

    // 3) softmax rows in place
    softmax_kernel<<<BATCH * SEQ, 256>>>(scores);

    // 4) attn_out = attn @ V   (B = V^T [1024][2048], K = 2048)
    gemm_mma<2><<<dim3(DIM / BN, SEQ / BM, BATCH), 256, SMEM_BYTES>>>(
        scores, SEQ, vT, SEQ, attn, DIM, SEQ,
        nullptr, nullptr, 0.f,
        (long)SEQ * SEQ, (long)DIM * SEQ, (long)SEQ * DIM, 0);

    // 5) out = attn_out @ Wout + bout
    gemm_mma<0><<<dim3(DIM / BN, M / BM, 1), 256, SMEM_BYTES>>>(
        attn, DIM, woutT, DIM, out, DIM, DIM,
        bout, nullptr, 0.f, 0, 0, 0, 0);
}

// round 4
// speedup vs baseline: 3.3576x; 1.0259x over previous
#include <cuda_runtime.h>
#include <cstdint>

#define BATCH 4
#define SEQ   2048
#define DIM   1024

// ---- scratch (alloc-free rule: __device__ globals) ----
__device__ float g_x32   [(size_t)BATCH * SEQ * DIM];       // x, tf32-rounded
__device__ float g_qkv   [(size_t)BATCH * SEQ * 3 * DIM];   // [8192][3072] tf32-rounded
__device__ float g_scores[(size_t)BATCH * SEQ * SEQ];       // [4][2048][2048]
__device__ float g_attn  [(size_t)BATCH * SEQ * DIM];       // [8192][1024] tf32-rounded
__device__ float g_wqkvT [(size_t)3 * DIM * DIM];           // [3072][1024] tf32-rounded
__device__ float g_woutT [(size_t)DIM * DIM];               // [1024][1024] tf32-rounded
__device__ float g_vT    [(size_t)BATCH * DIM * SEQ];       // [4][1024][2048] tf32-rounded

// =========================== PTX helpers ===========================
__device__ __forceinline__ uint32_t f2tf32(float x) {
    uint32_t r;
    asm("cvt.rna.tf32.f32 %0, %1;" : "=r"(r) : "f"(x));
    return r;
}
__device__ __forceinline__ float f2tf32f(float x) {
    return __uint_as_float(f2tf32(x));
}

__device__ __forceinline__ void mma_tf32(float* d, const uint32_t* a, const uint32_t* b) {
    asm volatile(
        "mma.sync.aligned.m16n8k8.row.col.f32.tf32.tf32.f32 "
        "{%0,%1,%2,%3}, {%4,%5,%6,%7}, {%8,%9}, {%0,%1,%2,%3};"
        : "+f"(d[0]), "+f"(d[1]), "+f"(d[2]), "+f"(d[3])
        : "r"(a[0]), "r"(a[1]), "r"(a[2]), "r"(a[3]), "r"(b[0]), "r"(b[1]));
}

__device__ __forceinline__ uint32_t smem_u32(const void* p) {
    uint32_t a;
    asm("{ .reg .u64 t; cvta.to.shared.u64 t, %1; cvt.u32.u64 %0, t; }"
        : "=r"(a) : "l"(p));
    return a;
}

#define CP_ASYNC16(dst_u32, src_ptr) \
    asm volatile("cp.async.cg.shared.global [%0], [%1], 16;" \
                 :: "r"(dst_u32), "l"(src_ptr) : "memory")
#define CP_COMMIT() asm volatile("cp.async.commit_group;" ::: "memory")
#define CP_WAIT(n)  asm volatile("cp.async.wait_group %0;" :: "n"(n) : "memory")

// =========================== GEMM (mma.sync tf32, cp.async 3-stage) ===========================
// C[M,N] = A[M,K] * B[N,K]^T.  A row-major [M,K], B row-major [N,K]; both pre-rounded to tf32.
// Block tile 128x256, BK=32. 256 threads = 8 warps (2 m x 4 n), warp tile 64x64.
// MODE 0: +bias[n]   MODE 1: *scale then mask==0 -> 1e-10   MODE 2: plain
// CVTOUT: round the written C to tf32 bits (it feeds a later GEMM as operand)

constexpr int BM = 128, BN = 256, BK = 32;
constexpr int LDS_ROW = BK + 4;                        // 36 floats, 144 B (multiple of 16)
constexpr int A_FLOATS = BM * LDS_ROW;                 // 4608
constexpr int B_FLOATS = BN * LDS_ROW;                 // 9216
constexpr int STAGE_FLOATS = A_FLOATS + B_FLOATS;      // 13824
constexpr int NSTAGE = 3;
constexpr int SMEM_BYTES = NSTAGE * STAGE_FLOATS * 4;  // 165888

template <int MODE, bool CVTOUT>
__global__ __launch_bounds__(256) void gemm_mma(
    const float* __restrict__ A, int lda,
    const float* __restrict__ B, int ldb,
    float* __restrict__ C, int ldc, int K,
    const float* __restrict__ bias,
    const int* __restrict__ mask, float scale,
    long sA, long sB, long sC, long sM)
{
    extern __shared__ uint32_t smem[];
    const uint32_t smem_base = smem_u32(smem);
    const int tid  = threadIdx.x;
    const int lane = tid & 31;
    const int wid  = tid >> 5;
    const int bz   = blockIdx.z;

    A += (long)bz * sA;
    B += (long)bz * sB;
    C += (long)bz * sC;
    if (MODE == 1) mask += (long)bz * sM;

    const int m0 = blockIdx.y * BM;
    const int n0 = blockIdx.x * BN;

    const int wm = (wid & 1) * 64;
    const int wn = (wid >> 1) * 64;
    const int lr = lane >> 2;          // 0..7
    const int lc = lane & 3;           // 0..3

    // per-thread load coords (A: 4 x 16B, B: 8 x 16B per stage)
    const int arow = tid >> 3;
    const int aq   = (tid & 7) * 4;    // k offset in floats (16B aligned)

    const float* Aped = A + (size_t)m0 * lda + aq;
    const float* Bped = B + (size_t)n0 * ldb + aq;
    const uint32_t a_dst0 = smem_base + (uint32_t)(arow * LDS_ROW + aq) * 4u;
    const uint32_t b_dst0 = smem_base + (uint32_t)(A_FLOATS + arow * LDS_ROW + aq) * 4u;

    const int NITER = K / BK;

    // ---- issue one stage's loads ----
    auto issue_stage = [&](int stage, int kc) {
        const uint32_t so = (uint32_t)(stage * STAGE_FLOATS * 4);
        const int kb = kc * BK;
        #pragma unroll
        for (int i = 0; i < 4; i++)
            CP_ASYNC16(a_dst0 + so + (uint32_t)(i * 32 * LDS_ROW * 4),
                       Aped + (size_t)(arow + i * 32) * lda + kb);
        #pragma unroll
        for (int i = 0; i < 8; i++)
            CP_ASYNC16(b_dst0 + so + (uint32_t)(i * 32 * LDS_ROW * 4),
                       Bped + (size_t)(arow + i * 32) * ldb + kb);
    };

    float acc[4][8][4];
    #pragma unroll
    for (int i = 0; i < 4; i++)
        #pragma unroll
        for (int j = 0; j < 8; j++)
            #pragma unroll
            for (int q = 0; q < 4; q++) acc[i][j][q] = 0.f;

    // prologue: stages 0 and 1
    issue_stage(0, 0); CP_COMMIT();
    issue_stage(1, 1); CP_COMMIT();

    #pragma unroll 1
    for (int kc = 0; kc < NITER; kc++) {
        CP_WAIT(1);
        __syncthreads();

        if (kc + 2 < NITER) issue_stage((kc + 2) % NSTAGE, kc + 2);
        CP_COMMIT();

        const uint32_t* As = smem + (kc % NSTAGE) * STAGE_FLOATS;
        const uint32_t* Bs = As + A_FLOATS;
        const uint32_t* Abase = As + (wm + lr) * LDS_ROW + lc;
        const uint32_t* Bbase = Bs + (wn + lr) * LDS_ROW + lc;

        #pragma unroll
        for (int kk = 0; kk < BK; kk += 8) {
            uint32_t a[4][4], b[8][2];
            #pragma unroll
            for (int mi = 0; mi < 4; mi++) {
                const uint32_t* p = Abase + mi * 16 * LDS_ROW + kk;
                a[mi][0] = p[0];
                a[mi][1] = p[8 * LDS_ROW];
                a[mi][2] = p[4];
                a[mi][3] = p[8 * LDS_ROW + 4];
            }
            #pragma unroll
            for (int ni = 0; ni < 8; ni++) {
                const uint32_t* p = Bbase + ni * 8 * LDS_ROW + kk;
                b[ni][0] = p[0];
                b[ni][1] = p[4];
            }
            #pragma unroll
            for (int mi = 0; mi < 4; mi++)
                #pragma unroll
                for (int ni = 0; ni < 8; ni++)
                    mma_tf32(acc[mi][ni], a[mi], b[ni]);
        }
    }

    // ---- epilogue ----
    #pragma unroll
    for (int mi = 0; mi < 4; mi++) {
        #pragma unroll
        for (int half = 0; half < 2; half++) {
            const int row = m0 + wm + mi * 16 + lr + half * 8;
            float* crow = C + (size_t)row * ldc;
            const int* mrow = (MODE == 1) ? (mask + (size_t)row * ldc) : nullptr;
            #pragma unroll
            for (int ni = 0; ni < 8; ni++) {
                const int col = n0 + wn + ni * 8 + lc * 2;
                float v0 = acc[mi][ni][half * 2 + 0];
                float v1 = acc[mi][ni][half * 2 + 1];
                if (MODE == 0) {
                    v0 += bias[col];
                    v1 += bias[col + 1];
                }
                if (MODE == 1) {
                    v0 *= scale; v1 *= scale;
                    const int2 mk = *(const int2*)(mrow + col);
                    if (mk.x == 0) v0 = 1e-10f;
                    if (mk.y == 0) v1 = 1e-10f;
                }
                if (CVTOUT) { v0 = f2tf32f(v0); v1 = f2tf32f(v1); }
                float2 v; v.x = v0; v.y = v1;
                *(float2*)(crow + col) = v;
            }
        }
    }
}

// =========================== convert (fp32 -> tf32 bits) ===========================
__global__ __launch_bounds__(256) void convert_kernel(
    const float* __restrict__ src, float* __restrict__ dst, size_t n4)
{
    size_t i = (size_t)blockIdx.x * 256 + threadIdx.x;
    if (i >= n4) return;
    float4 v = ((const float4*)src)[i];
    v.x = f2tf32f(v.x); v.y = f2tf32f(v.y);
    v.z = f2tf32f(v.z); v.w = f2tf32f(v.w);
    ((float4*)dst)[i] = v;
}

// =========================== transpose + convert ===========================
__global__ __launch_bounds__(256) void transpose_kernel(
    const float* __restrict__ src, float* __restrict__ dst,
    int srcLd, int dstLd, long sBatch, long dBatch)
{
    __shared__ float t[32][33];
    src += (long)blockIdx.z * sBatch;
    dst += (long)blockIdx.z * dBatch;
    const int c0 = blockIdx.x * 32, r0 = blockIdx.y * 32;
    const int tx = threadIdx.x, ty = threadIdx.y;
    #pragma unroll
    for (int i = 0; i < 32; i += 8)
        t[ty + i][tx] = f2tf32f(src[(size_t)(r0 + ty + i) * srcLd + c0 + tx]);
    __syncthreads();
    #pragma unroll
    for (int i = 0; i < 32; i += 8)
        dst[(size_t)(c0 + ty + i) * dstLd + r0 + tx] = t[tx][ty + i];
}

// =========================== softmax (writes tf32 bits) ===========================
__global__ __launch_bounds__(256) void softmax_kernel(float* __restrict__ s)
{
    const long row = blockIdx.x;
    float* p = s + row * SEQ;
    const int tid  = threadIdx.x;
    const int lane = tid & 31;
    const int warp = tid >> 5;

    __shared__ float redm[8];
    __shared__ float reds[8];

    float v[8];
    float m = -1e30f;
    #pragma unroll
    for (int i = 0; i < 8; i++) {
        v[i] = p[tid + i * 256];
        m = fmaxf(m, v[i]);
    }
    #pragma unroll
    for (int o = 16; o > 0; o >>= 1) m = fmaxf(m, __shfl_xor_sync(0xffffffffu, m, o));
    if (lane == 0) redm[warp] = m;
    __syncthreads();
    float M = redm[0];
    #pragma unroll
    for (int i = 1; i < 8; i++) M = fmaxf(M, redm[i]);

    float sum = 0.f;
    #pragma unroll
    for (int i = 0; i < 8; i++) {
        v[i] = expf(v[i] - M);
        sum += v[i];
    }
    #pragma unroll
    for (int o = 16; o > 0; o >>= 1) sum += __shfl_xor_sync(0xffffffffu, sum, o);
    if (lane == 0) reds[warp] = sum;
    __syncthreads();
    float total = 0.f;
    #pragma unroll
    for (int i = 0; i < 8; i++) total += reds[i];

    const float inv = 1.0f / total;
    #pragma unroll
    for (int i = 0; i < 8; i++) p[tid + i * 256] = f2tf32f(v[i] * inv);
}

// =========================== launch ===========================
extern "C" void kernel_launch(void* const* d_in, const int* in_sizes, int n_in,
                              void* d_out, int out_size)
{
    const float* x    = (const float*)d_in[0];
    const int*   mask = (const int*)  d_in[1];
    const float* Wqkv = (const float*)d_in[2];
    const float* bqkv = (const float*)d_in[3];
    const float* Wout = (const float*)d_in[4];
    const float* bout = (const float*)d_in[5];
    float* out = (float*)d_out;

    float* x32;    cudaGetSymbolAddress((void**)&x32,    g_x32);
    float* qkv;    cudaGetSymbolAddress((void**)&qkv,    g_qkv);
    float* scores; cudaGetSymbolAddress((void**)&scores, g_scores);
    float* attn;   cudaGetSymbolAddress((void**)&attn,   g_attn);
    float* wqkvT;  cudaGetSymbolAddress((void**)&wqkvT,  g_wqkvT);
    float* woutT;  cudaGetSymbolAddress((void**)&woutT,  g_woutT);
    float* vT;     cudaGetSymbolAddress((void**)&vT,     g_vT);

    cudaFuncSetAttribute(gemm_mma<0, true>,  cudaFuncAttributeMaxDynamicSharedMemorySize, SMEM_BYTES);
    cudaFuncSetAttribute(gemm_mma<0, false>, cudaFuncAttributeMaxDynamicSharedMemorySize, SMEM_BYTES);
    cudaFuncSetAttribute(gemm_mma<1, false>, cudaFuncAttributeMaxDynamicSharedMemorySize, SMEM_BYTES);
    cudaFuncSetAttribute(gemm_mma<2, true>,  cudaFuncAttributeMaxDynamicSharedMemorySize, SMEM_BYTES);

    const float scale = 0.03125f;  // 1/sqrt(1024)
    const int M = BATCH * SEQ;     // 8192

    // convert x -> tf32 bits
    {
        size_t n4 = (size_t)M * DIM / 4;   // 2M float4
        convert_kernel<<<(unsigned)((n4 + 255) / 256), 256>>>(x, x32, n4);
    }
    // transpose+convert weights
    transpose_kernel<<<dim3(3 * DIM / 32, DIM / 32, 1), dim3(32, 8)>>>(
        Wqkv, wqkvT, 3 * DIM, DIM, 0, 0);
    transpose_kernel<<<dim3(DIM / 32, DIM / 32, 1), dim3(32, 8)>>>(
        Wout, woutT, DIM, DIM, 0, 0);

    // 1) qkv = x @ Wqkv + bqkv   (written tf32-rounded)
    gemm_mma<0, true><<<dim3(3 * DIM / BN, M / BM, 1), 256, SMEM_BYTES>>>(
        x32, DIM, wqkvT, DIM, qkv, 3 * DIM, DIM,
        bqkv, nullptr, 0.f, 0, 0, 0, 0);

    // transpose V per batch: vT [4][1024][2048]
    transpose_kernel<<<dim3(DIM / 32, SEQ / 32, BATCH), dim3(32, 8)>>>(
        qkv + 2 * DIM, vT, 3 * DIM, SEQ, (long)SEQ * 3 * DIM, (long)DIM * SEQ);

    // 2) scores = Q @ K^T * scale, mask==0 -> 1e-10  (fp32; softmax rounds on write)
    gemm_mma<1, false><<<dim3(SEQ / BN, SEQ / BM, BATCH), 256, SMEM_BYTES>>>(
        qkv, 3 * DIM, qkv + DIM, 3 * DIM, scores, SEQ, DIM,
        nullptr, mask, scale,
        (long)SEQ * 3 * DIM, (long)SEQ * 3 * DIM, (long)SEQ * SEQ, (long)SEQ * SEQ);

    // 3) softmax rows in place (writes tf32-rounded)
    softmax_kernel<<<BATCH * SEQ, 256>>>(scores);

    // 4) attn_out = attn @ V    (written tf32-rounded)
    gemm_mma<2, true><<<dim3(DIM / BN, SEQ / BM, BATCH), 256, SMEM_BYTES>>>(
        scores, SEQ, vT, SEQ, attn, DIM, SEQ,
        nullptr, nullptr, 0.f,
        (long)SEQ * SEQ, (long)DIM * SEQ, (long)SEQ * DIM, 0);

    // 5) out = attn_out @ Wout + bout  (exact fp32 out)
    gemm_mma<0, false><<<dim3(DIM / BN, M / BM, 1), 256, SMEM_BYTES>>>(
        attn, DIM, woutT, DIM, out, DIM, DIM,
        bout, nullptr, 0.f, 0, 0, 0, 0);
}

// round 5
// speedup vs baseline: 5.2372x; 1.5598x over previous
#include <cuda_runtime.h>
#include <cuda_fp16.h>
#include <cstdint>

#define BATCH 4
#define SEQ   2048
#define DIM   1024

// ---- scratch (alloc-free rule: __device__ globals) ----
__device__ __half g_x16  [(size_t)BATCH * SEQ * DIM];       // x -> half
__device__ __half g_qkv  [(size_t)BATCH * SEQ * 3 * DIM];   // [8192][3072] half
__device__ float  g_scores[(size_t)BATCH * SEQ * SEQ];      // [4][2048][2048] fp32
__device__ __half g_probs[(size_t)BATCH * SEQ * SEQ];       // softmax(scores) half
__device__ __half g_attn [(size_t)BATCH * SEQ * DIM];       // [8192][1024] half
__device__ __half g_wqkvT[(size_t)3 * DIM * DIM];           // [3072][1024] half
__device__ __half g_woutT[(size_t)DIM * DIM];               // [1024][1024] half
__device__ __half g_vT   [(size_t)BATCH * DIM * SEQ];       // [4][1024][2048] half

// =========================== PTX helpers ===========================
__device__ __forceinline__ void mma_f16(float* d, const uint32_t* a, const uint32_t* b) {
    asm volatile(
        "mma.sync.aligned.m16n8k16.row.col.f32.f16.f16.f32 "
        "{%0,%1,%2,%3}, {%4,%5,%6,%7}, {%8,%9}, {%0,%1,%2,%3};"
        : "+f"(d[0]), "+f"(d[1]), "+f"(d[2]), "+f"(d[3])
        : "r"(a[0]), "r"(a[1]), "r"(a[2]), "r"(a[3]), "r"(b[0]), "r"(b[1]));
}

__device__ __forceinline__ uint32_t smem_u32(const void* p) {
    uint32_t a;
    asm("{ .reg .u64 t; cvta.to.shared.u64 t, %1; cvt.u32.u64 %0, t; }"
        : "=r"(a) : "l"(p));
    return a;
}

#define CP_ASYNC16(dst_u32, src_ptr) \
    asm volatile("cp.async.cg.shared.global [%0], [%1], 16;" \
                 :: "r"(dst_u32), "l"(src_ptr) : "memory")
#define CP_COMMIT() asm volatile("cp.async.commit_group;" ::: "memory")
#define CP_WAIT(n)  asm volatile("cp.async.wait_group %0;" :: "n"(n) : "memory")

// =========================== GEMM (mma.sync f16 k16, cp.async 3-stage) ===========================
// C[M,N] = A[M,K] * B[N,K]^T.  A, B half, row-major with K contiguous.
// Block tile 128x256, BK=32. 256 threads = 8 warps (2m x 4n), warp tile 64x64.
// MODE 0: +bias[n]   MODE 1: *scale then mask==0 -> 1e-10   MODE 2: plain
// OUTH: write C as half (feeds a later GEMM); else fp32.

constexpr int BM = 128, BN = 256, BK = 32;
constexpr int ROW_HALFS = 40;                          // 32 data + 8 pad, 80 B pitch
constexpr int A_HALFS = BM * ROW_HALFS;                // 5120
constexpr int B_HALFS = BN * ROW_HALFS;                // 10240
constexpr int STAGE_HALFS = A_HALFS + B_HALFS;         // 15360
constexpr int NSTAGE = 3;
constexpr int SMEM_BYTES = NSTAGE * STAGE_HALFS * 2;   // 92160

template <int MODE, bool OUTH>
__global__ __launch_bounds__(256) void gemm_f16k(
    const __half* __restrict__ A, int lda,
    const __half* __restrict__ B, int ldb,
    void* __restrict__ Cv, int ldc, int K,
    const float* __restrict__ bias,
    const int* __restrict__ mask, float scale,
    long sA, long sB, long sC, long sM)
{
    extern __shared__ __half smem[];
    const uint32_t smem_base = smem_u32(smem);
    const int tid  = threadIdx.x;
    const int lane = tid & 31;
    const int wid  = tid >> 5;
    const int bz   = blockIdx.z;

    A += (long)bz * sA;
    B += (long)bz * sB;
    if (MODE == 1) mask += (long)bz * sM;

    const int m0 = blockIdx.y * BM;
    const int n0 = blockIdx.x * BN;

    const int wm = (wid & 1) * 64;
    const int wn = (wid >> 1) * 64;
    const int lr = lane >> 2;          // 0..7
    const int lc = lane & 3;           // 0..3

    // per-thread load coords: row = tid>>2 (+strides), quad = tid&3 (16B chunk of 64B row)
    const int lrow = tid >> 2;
    const int lq   = (tid & 3) * 8;    // halfs offset (16 B)

    const __half* Aped = A + (size_t)(m0 + lrow) * lda + lq;
    const __half* Bped = B + (size_t)(n0 + lrow) * ldb + lq;
    const uint32_t a_dst0 = smem_base + (uint32_t)(lrow * ROW_HALFS + lq) * 2u;
    const uint32_t b_dst0 = smem_base + (uint32_t)((A_HALFS + lrow * ROW_HALFS + lq)) * 2u;

    const int NITER = K / BK;

    auto issue_stage = [&](int stage, int kc) {
        const uint32_t so = (uint32_t)(stage * STAGE_HALFS * 2);
        const int kb = kc * BK;
        #pragma unroll
        for (int i = 0; i < 2; i++)     // A: 128 rows, 64/iter
            CP_ASYNC16(a_dst0 + so + (uint32_t)(i * 64 * ROW_HALFS * 2),
                       Aped + (size_t)(i * 64) * lda + kb);
        #pragma unroll
        for (int i = 0; i < 4; i++)     // B: 256 rows, 64/iter
            CP_ASYNC16(b_dst0 + so + (uint32_t)(i * 64 * ROW_HALFS * 2),
                       Bped + (size_t)(i * 64) * ldb + kb);
    };

    float acc[4][8][4];
    #pragma unroll
    for (int i = 0; i < 4; i++)
        #pragma unroll
        for (int j = 0; j < 8; j++)
            #pragma unroll
            for (int q = 0; q < 4; q++) acc[i][j][q] = 0.f;

    issue_stage(0, 0); CP_COMMIT();
    issue_stage(1, 1); CP_COMMIT();

    #pragma unroll 1
    for (int kc = 0; kc < NITER; kc++) {
        CP_WAIT(1);
        __syncthreads();

        if (kc + 2 < NITER) issue_stage((kc + 2) % NSTAGE, kc + 2);
        CP_COMMIT();

        const __half* As = smem + (kc % NSTAGE) * STAGE_HALFS;
        const __half* Bs = As + A_HALFS;
        const __half* Abase = As + (wm + lr) * ROW_HALFS + 2 * lc;
        const __half* Bbase = Bs + (wn + lr) * ROW_HALFS + 2 * lc;

        #pragma unroll
        for (int kk = 0; kk < BK; kk += 16) {
            uint32_t a[4][4], b[8][2];
            #pragma unroll
            for (int mi = 0; mi < 4; mi++) {
                const __half* p = Abase + mi * 16 * ROW_HALFS + kk;
                a[mi][0] = *(const uint32_t*)(p);
                a[mi][1] = *(const uint32_t*)(p + 8 * ROW_HALFS);
                a[mi][2] = *(const uint32_t*)(p + 8);
                a[mi][3] = *(const uint32_t*)(p + 8 * ROW_HALFS + 8);
            }
            #pragma unroll
            for (int ni = 0; ni < 8; ni++) {
                const __half* p = Bbase + ni * 8 * ROW_HALFS + kk;
                b[ni][0] = *(const uint32_t*)(p);
                b[ni][1] = *(const uint32_t*)(p + 8);
            }
            #pragma unroll
            for (int mi = 0; mi < 4; mi++)
                #pragma unroll
                for (int ni = 0; ni < 8; ni++)
                    mma_f16(acc[mi][ni], a[mi], b[ni]);
        }
    }

    // ---- epilogue ----
    #pragma unroll
    for (int mi = 0; mi < 4; mi++) {
        #pragma unroll
        for (int half_ = 0; half_ < 2; half_++) {
            const int row = m0 + wm + mi * 16 + lr + half_ * 8;
            const int* mrow = (MODE == 1) ? (mask + (size_t)row * ldc) : nullptr;
            #pragma unroll
            for (int ni = 0; ni < 8; ni++) {
                const int col = n0 + wn + ni * 8 + lc * 2;
                float v0 = acc[mi][ni][half_ * 2 + 0];
                float v1 = acc[mi][ni][half_ * 2 + 1];
                if (MODE == 0) {
                    v0 += bias[col];
                    v1 += bias[col + 1];
                }
                if (MODE == 1) {
                    v0 *= scale; v1 *= scale;
                    const int2 mk = *(const int2*)(mrow + col);
                    if (mk.x == 0) v0 = 1e-10f;
                    if (mk.y == 0) v1 = 1e-10f;
                }
                if (OUTH) {
                    __half* C = (__half*)Cv + (long)bz * sC + (size_t)row * ldc + col;
                    *(__half2*)C = __floats2half2_rn(v0, v1);
                } else {
                    float* C = (float*)Cv + (long)bz * sC + (size_t)row * ldc + col;
                    float2 v; v.x = v0; v.y = v1;
                    *(float2*)C = v;
                }
            }
        }
    }
}

// =========================== convert x: fp32 -> half ===========================
__global__ __launch_bounds__(256) void convert_kernel(
    const float* __restrict__ src, __half* __restrict__ dst, size_t n4)
{
    size_t i = (size_t)blockIdx.x * 256 + threadIdx.x;
    if (i >= n4) return;
    float4 v = ((const float4*)src)[i];
    __half2 h0 = __floats2half2_rn(v.x, v.y);
    __half2 h1 = __floats2half2_rn(v.z, v.w);
    ((__half2*)dst)[i * 2]     = h0;
    ((__half2*)dst)[i * 2 + 1] = h1;
}

// =========================== transpose fp32 -> half ===========================
__global__ __launch_bounds__(256) void transpose_f2h(
    const float* __restrict__ src, __half* __restrict__ dst,
    int srcLd, int dstLd)
{
    __shared__ float t[32][33];
    const int c0 = blockIdx.x * 32, r0 = blockIdx.y * 32;
    const int tx = threadIdx.x, ty = threadIdx.y;
    #pragma unroll
    for (int i = 0; i < 32; i += 8)
        t[ty + i][tx] = src[(size_t)(r0 + ty + i) * srcLd + c0 + tx];
    __syncthreads();
    #pragma unroll
    for (int i = 0; i < 32; i += 8)
        dst[(size_t)(c0 + ty + i) * dstLd + r0 + tx] = __float2half(t[tx][ty + i]);
}

// =========================== transpose half -> half ===========================
__global__ __launch_bounds__(256) void transpose_h2h(
    const __half* __restrict__ src, __half* __restrict__ dst,
    int srcLd, int dstLd, long sBatch, long dBatch)
{
    __shared__ __half t[32][34];
    src += (long)blockIdx.z * sBatch;
    dst += (long)blockIdx.z * dBatch;
    const int c0 = blockIdx.x * 32, r0 = blockIdx.y * 32;
    const int tx = threadIdx.x, ty = threadIdx.y;
    #pragma unroll
    for (int i = 0; i < 32; i += 8)
        t[ty + i][tx] = src[(size_t)(r0 + ty + i) * srcLd + c0 + tx];
    __syncthreads();
    #pragma unroll
    for (int i = 0; i < 32; i += 8)
        dst[(size_t)(c0 + ty + i) * dstLd + r0 + tx] = t[tx][ty + i];
}

// =========================== softmax: fp32 scores -> half probs ===========================
__global__ __launch_bounds__(256) void softmax_kernel(
    const float* __restrict__ s, __half* __restrict__ o)
{
    const long row = blockIdx.x;
    const float* p = s + row * SEQ;
    __half* q = o + row * SEQ;
    const int tid  = threadIdx.x;
    const int lane = tid & 31;
    const int warp = tid >> 5;

    __shared__ float redm[8];
    __shared__ float reds[8];

    float v[8];
    float m = -1e30f;
    #pragma unroll
    for (int i = 0; i < 8; i++) {
        v[i] = p[tid + i * 256];
        m = fmaxf(m, v[i]);
    }
    #pragma unroll
    for (int oo = 16; oo > 0; oo >>= 1) m = fmaxf(m, __shfl_xor_sync(0xffffffffu, m, oo));
    if (lane == 0) redm[warp] = m;
    __syncthreads();
    float M = redm[0];
    #pragma unroll
    for (int i = 1; i < 8; i++) M = fmaxf(M, redm[i]);

    float sum = 0.f;
    #pragma unroll
    for (int i = 0; i < 8; i++) {
        v[i] = expf(v[i] - M);
        sum += v[i];
    }
    #pragma unroll
    for (int oo = 16; oo > 0; oo >>= 1) sum += __shfl_xor_sync(0xffffffffu, sum, oo);
    if (lane == 0) reds[warp] = sum;
    __syncthreads();
    float total = 0.f;
    #pragma unroll
    for (int i = 0; i < 8; i++) total += reds[i];

    const float inv = 1.0f / total;
    #pragma unroll
    for (int i = 0; i < 8; i++) q[tid + i * 256] = __float2half(v[i] * inv);
}

// =========================== launch ===========================
extern "C" void kernel_launch(void* const* d_in, const int* in_sizes, int n_in,
                              void* d_out, int out_size)
{
    const float* x    = (const float*)d_in[0];
    const int*   mask = (const int*)  d_in[1];
    const float* Wqkv = (const float*)d_in[2];
    const float* bqkv = (const float*)d_in[3];
    const float* Wout = (const float*)d_in[4];
    const float* bout = (const float*)d_in[5];
    float* out = (float*)d_out;

    __half* x16;   cudaGetSymbolAddress((void**)&x16,   g_x16);
    __half* qkv;   cudaGetSymbolAddress((void**)&qkv,   g_qkv);
    float*  scores;cudaGetSymbolAddress((void**)&scores,g_scores);
    __half* probs; cudaGetSymbolAddress((void**)&probs, g_probs);
    __half* attn;  cudaGetSymbolAddress((void**)&attn,  g_attn);
    __half* wqkvT; cudaGetSymbolAddress((void**)&wqkvT, g_wqkvT);
    __half* woutT; cudaGetSymbolAddress((void**)&woutT, g_woutT);
    __half* vT;    cudaGetSymbolAddress((void**)&vT,    g_vT);

    cudaFuncSetAttribute(gemm_f16k<0, true>,  cudaFuncAttributeMaxDynamicSharedMemorySize, SMEM_BYTES);
    cudaFuncSetAttribute(gemm_f16k<0, false>, cudaFuncAttributeMaxDynamicSharedMemorySize, SMEM_BYTES);
    cudaFuncSetAttribute(gemm_f16k<1, false>, cudaFuncAttributeMaxDynamicSharedMemorySize, SMEM_BYTES);
    cudaFuncSetAttribute(gemm_f16k<2, true>,  cudaFuncAttributeMaxDynamicSharedMemorySize, SMEM_BYTES);

    const float scale = 0.03125f;  // 1/sqrt(1024)
    const int M = BATCH * SEQ;     // 8192

    // x -> half
    {
        size_t n4 = (size_t)M * DIM / 4;
        convert_kernel<<<(unsigned)((n4 + 255) / 256), 256>>>(x, x16, n4);
    }
    // weights: transpose + convert
    transpose_f2h<<<dim3(3 * DIM / 32, DIM / 32, 1), dim3(32, 8)>>>(Wqkv, wqkvT, 3 * DIM, DIM);
    transpose_f2h<<<dim3(DIM / 32, DIM / 32, 1), dim3(32, 8)>>>(Wout, woutT, DIM, DIM);

    // 1) qkv = x @ Wqkv + bqkv  (half out)
    gemm_f16k<0, true><<<dim3(3 * DIM / BN, M / BM, 1), 256, SMEM_BYTES>>>(
        x16, DIM, wqkvT, DIM, qkv, 3 * DIM, DIM,
        bqkv, nullptr, 0.f, 0, 0, 0, 0);

    // V transpose per batch: vT [4][1024][2048]
    transpose_h2h<<<dim3(DIM / 32, SEQ / 32, BATCH), dim3(32, 8)>>>(
        qkv + 2 * DIM, vT, 3 * DIM, SEQ, (long)SEQ * 3 * DIM, (long)DIM * SEQ);

    // 2) scores = Q @ K^T * scale, mask==0 -> 1e-10  (fp32 out)
    gemm_f16k<1, false><<<dim3(SEQ / BN, SEQ / BM, BATCH), 256, SMEM_BYTES>>>(
        qkv, 3 * DIM, qkv + DIM, 3 * DIM, scores, SEQ, DIM,
        nullptr, mask, scale,
        (long)SEQ * 3 * DIM, (long)SEQ * 3 * DIM, (long)SEQ * SEQ, (long)SEQ * SEQ);

    // 3) softmax -> half probs
    softmax_kernel<<<BATCH * SEQ, 256>>>(scores, probs);

    // 4) attn_out = probs @ V  (half out)
    gemm_f16k<2, true><<<dim3(DIM / BN, SEQ / BM, BATCH), 256, SMEM_BYTES>>>(
        probs, SEQ, vT, SEQ, attn, DIM, SEQ,
        nullptr, nullptr, 0.f,
        (long)SEQ * SEQ, (long)DIM * SEQ, (long)SEQ * DIM, 0);

    // 5) out = attn_out @ Wout + bout  (fp32 out)
    gemm_f16k<0, false><<<dim3(DIM / BN, M / BM, 1), 256, SMEM_BYTES>>>(
        attn, DIM, woutT, DIM, out, DIM, DIM,
        bout, nullptr, 0.f, 0, 0, 0, 0);
}

// round 6
// speedup vs baseline: 6.2002x; 1.1839x over previous
#include <cuda_runtime.h>
#include <cuda_fp16.h>
#include <cstdint>

#define BATCH 4
#define SEQ   2048
#define DIM   1024

// ---- scratch (alloc-free rule: __device__ globals) ----
__device__ __half g_x16  [(size_t)BATCH * SEQ * DIM];       // x -> half
__device__ __half g_qkv  [(size_t)BATCH * SEQ * 3 * DIM];   // [8192][3072] half
__device__ float  g_scores[(size_t)BATCH * SEQ * SEQ];      // [4][2048][2048] fp32
__device__ __half g_probs[(size_t)BATCH * SEQ * SEQ];       // softmax(scores) half
__device__ __half g_attn [(size_t)BATCH * SEQ * DIM];       // [8192][1024] half
__device__ __half g_wqkvT[(size_t)3 * DIM * DIM];           // [3072][1024] half
__device__ __half g_woutT[(size_t)DIM * DIM];               // [1024][1024] half
__device__ __half g_vT   [(size_t)BATCH * DIM * SEQ];       // [4][1024][2048] half

// =========================== PTX helpers ===========================
__device__ __forceinline__ void mma_f16(float* d, const uint32_t* a, const uint32_t* b) {
    asm volatile(
        "mma.sync.aligned.m16n8k16.row.col.f32.f16.f16.f32 "
        "{%0,%1,%2,%3}, {%4,%5,%6,%7}, {%8,%9}, {%0,%1,%2,%3};"
        : "+f"(d[0]), "+f"(d[1]), "+f"(d[2]), "+f"(d[3])
        : "r"(a[0]), "r"(a[1]), "r"(a[2]), "r"(a[3]), "r"(b[0]), "r"(b[1]));
}

__device__ __forceinline__ void ldsm_x4(uint32_t* r, uint32_t addr) {
    asm volatile("ldmatrix.sync.aligned.m8n8.x4.shared.b16 {%0,%1,%2,%3}, [%4];"
        : "=r"(r[0]), "=r"(r[1]), "=r"(r[2]), "=r"(r[3]) : "r"(addr));
}

__device__ __forceinline__ uint32_t smem_u32(const void* p) {
    uint32_t a;
    asm("{ .reg .u64 t; cvta.to.shared.u64 t, %1; cvt.u32.u64 %0, t; }"
        : "=r"(a) : "l"(p));
    return a;
}

#define CP_ASYNC16(dst_u32, src_ptr) \
    asm volatile("cp.async.cg.shared.global [%0], [%1], 16;" \
                 :: "r"(dst_u32), "l"(src_ptr) : "memory")
#define CP_COMMIT() asm volatile("cp.async.commit_group;" ::: "memory")
#define CP_WAIT(n)  asm volatile("cp.async.wait_group %0;" :: "n"(n) : "memory")

// =========================== GEMM (mma f16 k16, ldmatrix, cp.async 3-stage) ====================
// C[M,N] = A[M,K] * B[N,K]^T.  A, B half, K contiguous.
// Block tile 128x128, BK=32. 256 threads = 8 warps (2m x 4n), warp tile 64x32. 2 CTAs/SM.
// MODE 0: +bias[n]   MODE 1: *scale then mask==0 -> 1e-10   MODE 2: plain
// OUTH: write C as half; else fp32.

constexpr int BM = 128, BN = 128, BK = 32;
constexpr int ROW_HALFS = 40;                          // 32 data + 8 pad, 80 B pitch
constexpr int ROW_BYTES = ROW_HALFS * 2;               // 80
constexpr int A_HALFS = BM * ROW_HALFS;                // 5120
constexpr int B_HALFS = BN * ROW_HALFS;                // 5120
constexpr int STAGE_HALFS = A_HALFS + B_HALFS;         // 10240
constexpr int STAGE_BYTES = STAGE_HALFS * 2;           // 20480
constexpr int NSTAGE = 3;
constexpr int SMEM_BYTES = NSTAGE * STAGE_BYTES;       // 61440

template <int MODE, bool OUTH>
__global__ __launch_bounds__(256, 2) void gemm_f16k(
    const __half* __restrict__ A, int lda,
    const __half* __restrict__ B, int ldb,
    void* __restrict__ Cv, int ldc, int K,
    const float* __restrict__ bias,
    const int* __restrict__ mask, float scale,
    long sA, long sB, long sC, long sM)
{
    extern __shared__ __half smem[];
    const uint32_t smem_base = smem_u32(smem);
    const int tid  = threadIdx.x;
    const int lane = tid & 31;
    const int wid  = tid >> 5;
    const int bz   = blockIdx.z;

    A += (long)bz * sA;
    B += (long)bz * sB;
    if (MODE == 1) mask += (long)bz * sM;

    const int m0 = blockIdx.y * BM;
    const int n0 = blockIdx.x * BN;

    const int wm = (wid & 1) * 64;     // warp m offset
    const int wn = (wid >> 1) * 32;    // warp n offset

    // ldmatrix per-lane byte offsets within a tile
    // A (m16k16 fragments): row = lane&15, koffset = (lane>>4)*8 halfs
    const uint32_t a_lane = (uint32_t)((lane & 15) * ROW_BYTES + (lane >> 4) * 16);
    // B (n16k16 fragments): n = (lane&7) + ((lane>>4)<<3), koffset = ((lane>>3)&1)*8 halfs
    const uint32_t b_lane = (uint32_t)(((lane & 7) + ((lane >> 4) << 3)) * ROW_BYTES
                                       + ((lane >> 3) & 1) * 16);

    const uint32_t a_warp = smem_base + (uint32_t)(wm * ROW_BYTES) + a_lane;
    const uint32_t b_warp = smem_base + (uint32_t)(A_HALFS * 2 + wn * ROW_BYTES) + b_lane;

    // cp.async coords: row = tid>>2 (0..63, +64 stride), 16B chunk = (tid&3)*16B
    const int lrow = tid >> 2;
    const int lq   = (tid & 3) * 8;    // halfs

    const __half* Aped = A + (size_t)(m0 + lrow) * lda + lq;
    const __half* Bped = B + (size_t)(n0 + lrow) * ldb + lq;
    const uint32_t a_dst0 = smem_base + (uint32_t)(lrow * ROW_BYTES + lq * 2);
    const uint32_t b_dst0 = smem_base + (uint32_t)(A_HALFS * 2 + lrow * ROW_BYTES + lq * 2);

    const int NITER = K / BK;

    auto issue_stage = [&](int stage, int kc) {
        const uint32_t so = (uint32_t)(stage * STAGE_BYTES);
        const int kb = kc * BK;
        #pragma unroll
        for (int i = 0; i < 2; i++)
            CP_ASYNC16(a_dst0 + so + (uint32_t)(i * 64 * ROW_BYTES),
                       Aped + (size_t)(i * 64) * lda + kb);
        #pragma unroll
        for (int i = 0; i < 2; i++)
            CP_ASYNC16(b_dst0 + so + (uint32_t)(i * 64 * ROW_BYTES),
                       Bped + (size_t)(i * 64) * ldb + kb);
    };

    float acc[4][4][4];
    #pragma unroll
    for (int i = 0; i < 4; i++)
        #pragma unroll
        for (int j = 0; j < 4; j++)
            #pragma unroll
            for (int q = 0; q < 4; q++) acc[i][j][q] = 0.f;

    issue_stage(0, 0); CP_COMMIT();
    issue_stage(1, 1); CP_COMMIT();

    #pragma unroll 1
    for (int kc = 0; kc < NITER; kc++) {
        CP_WAIT(1);
        __syncthreads();

        if (kc + 2 < NITER) issue_stage((kc + 2) % NSTAGE, kc + 2);
        CP_COMMIT();

        const uint32_t so = (uint32_t)((kc % NSTAGE) * STAGE_BYTES);
        const uint32_t a_base = a_warp + so;
        const uint32_t b_base = b_warp + so;

        #pragma unroll
        for (int kk = 0; kk < BK; kk += 16) {
            uint32_t a[4][4], b[4][2];
            #pragma unroll
            for (int mi = 0; mi < 4; mi++)
                ldsm_x4(a[mi], a_base + (uint32_t)(mi * 16 * ROW_BYTES + kk * 2));
            #pragma unroll
            for (int nj = 0; nj < 2; nj++) {
                uint32_t t[4];
                ldsm_x4(t, b_base + (uint32_t)(nj * 16 * ROW_BYTES + kk * 2));
                b[nj * 2 + 0][0] = t[0]; b[nj * 2 + 0][1] = t[1];
                b[nj * 2 + 1][0] = t[2]; b[nj * 2 + 1][1] = t[3];
            }
            #pragma unroll
            for (int mi = 0; mi < 4; mi++)
                #pragma unroll
                for (int ni = 0; ni < 4; ni++)
                    mma_f16(acc[mi][ni], a[mi], b[ni]);
        }
    }

    // ---- epilogue ----
    const int lr = lane >> 2;
    const int lc = lane & 3;
    #pragma unroll
    for (int mi = 0; mi < 4; mi++) {
        #pragma unroll
        for (int half_ = 0; half_ < 2; half_++) {
            const int row = m0 + wm + mi * 16 + lr + half_ * 8;
            const int* mrow = (MODE == 1) ? (mask + (size_t)row * ldc) : nullptr;
            #pragma unroll
            for (int ni = 0; ni < 4; ni++) {
                const int col = n0 + wn + ni * 8 + lc * 2;
                float v0 = acc[mi][ni][half_ * 2 + 0];
                float v1 = acc[mi][ni][half_ * 2 + 1];
                if (MODE == 0) {
                    v0 += bias[col];
                    v1 += bias[col + 1];
                }
                if (MODE == 1) {
                    v0 *= scale; v1 *= scale;
                    const int2 mk = *(const int2*)(mrow + col);
                    if (mk.x == 0) v0 = 1e-10f;
                    if (mk.y == 0) v1 = 1e-10f;
                }
                if (OUTH) {
                    __half* C = (__half*)Cv + (long)bz * sC + (size_t)row * ldc + col;
                    *(__half2*)C = __floats2half2_rn(v0, v1);
                } else {
                    float* C = (float*)Cv + (long)bz * sC + (size_t)row * ldc + col;
                    float2 v; v.x = v0; v.y = v1;
                    *(float2*)C = v;
                }
            }
        }
    }
}

// =========================== convert x: fp32 -> half ===========================
__global__ __launch_bounds__(256) void convert_kernel(
    const float* __restrict__ src, __half* __restrict__ dst, size_t n4)
{
    size_t i = (size_t)blockIdx.x * 256 + threadIdx.x;
    if (i >= n4) return;
    float4 v = ((const float4*)src)[i];
    ((__half2*)dst)[i * 2]     = __floats2half2_rn(v.x, v.y);
    ((__half2*)dst)[i * 2 + 1] = __floats2half2_rn(v.z, v.w);
}

// =========================== transpose fp32 -> half ===========================
__global__ __launch_bounds__(256) void transpose_f2h(
    const float* __restrict__ src, __half* __restrict__ dst,
    int srcLd, int dstLd)
{
    __shared__ float t[32][33];
    const int c0 = blockIdx.x * 32, r0 = blockIdx.y * 32;
    const int tx = threadIdx.x, ty = threadIdx.y;
    #pragma unroll
    for (int i = 0; i < 32; i += 8)
        t[ty + i][tx] = src[(size_t)(r0 + ty + i) * srcLd + c0 + tx];
    __syncthreads();
    #pragma unroll
    for (int i = 0; i < 32; i += 8)
        dst[(size_t)(c0 + ty + i) * dstLd + r0 + tx] = __float2half(t[tx][ty + i]);
}

// =========================== transpose half -> half ===========================
__global__ __launch_bounds__(256) void transpose_h2h(
    const __half* __restrict__ src, __half* __restrict__ dst,
    int srcLd, int dstLd, long sBatch, long dBatch)
{
    __shared__ __half t[32][34];
    src += (long)blockIdx.z * sBatch;
    dst += (long)blockIdx.z * dBatch;
    const int c0 = blockIdx.x * 32, r0 = blockIdx.y * 32;
    const int tx = threadIdx.x, ty = threadIdx.y;
    #pragma unroll
    for (int i = 0; i < 32; i += 8)
        t[ty + i][tx] = src[(size_t)(r0 + ty + i) * srcLd + c0 + tx];
    __syncthreads();
    #pragma unroll
    for (int i = 0; i < 32; i += 8)
        dst[(size_t)(c0 + ty + i) * dstLd + r0 + tx] = t[tx][ty + i];
}

// =========================== softmax: fp32 scores -> half probs ===========================
__global__ __launch_bounds__(256) void softmax_kernel(
    const float* __restrict__ s, __half* __restrict__ o)
{
    const long row = blockIdx.x;
    const float* p = s + row * SEQ;
    __half* q = o + row * SEQ;
    const int tid  = threadIdx.x;
    const int lane = tid & 31;
    const int warp = tid >> 5;

    __shared__ float redm[8];
    __shared__ float reds[8];

    float v[8];
    float m = -1e30f;
    #pragma unroll
    for (int i = 0; i < 8; i++) {
        v[i] = p[tid + i * 256];
        m = fmaxf(m, v[i]);
    }
    #pragma unroll
    for (int oo = 16; oo > 0; oo >>= 1) m = fmaxf(m, __shfl_xor_sync(0xffffffffu, m, oo));
    if (lane == 0) redm[warp] = m;
    __syncthreads();
    float M = redm[0];
    #pragma unroll
    for (int i = 1; i < 8; i++) M = fmaxf(M, redm[i]);

    float sum = 0.f;
    #pragma unroll
    for (int i = 0; i < 8; i++) {
        v[i] = expf(v[i] - M);
        sum += v[i];
    }
    #pragma unroll
    for (int oo = 16; oo > 0; oo >>= 1) sum += __shfl_xor_sync(0xffffffffu, sum, oo);
    if (lane == 0) reds[warp] = sum;
    __syncthreads();
    float total = 0.f;
    #pragma unroll
    for (int i = 0; i < 8; i++) total += reds[i];

    const float inv = 1.0f / total;
    #pragma unroll
    for (int i = 0; i < 8; i++) q[tid + i * 256] = __float2half(v[i] * inv);
}

// =========================== launch ===========================
extern "C" void kernel_launch(void* const* d_in, const int* in_sizes, int n_in,
                              void* d_out, int out_size)
{
    const float* x    = (const float*)d_in[0];
    const int*   mask = (const int*)  d_in[1];
    const float* Wqkv = (const float*)d_in[2];
    const float* bqkv = (const float*)d_in[3];
    const float* Wout = (const float*)d_in[4];
    const float* bout = (const float*)d_in[5];
    float* out = (float*)d_out;

    __half* x16;   cudaGetSymbolAddress((void**)&x16,   g_x16);
    __half* qkv;   cudaGetSymbolAddress((void**)&qkv,   g_qkv);
    float*  scores;cudaGetSymbolAddress((void**)&scores,g_scores);
    __half* probs; cudaGetSymbolAddress((void**)&probs, g_probs);
    __half* attn;  cudaGetSymbolAddress((void**)&attn,  g_attn);
    __half* wqkvT; cudaGetSymbolAddress((void**)&wqkvT, g_wqkvT);
    __half* woutT; cudaGetSymbolAddress((void**)&woutT, g_woutT);
    __half* vT;    cudaGetSymbolAddress((void**)&vT,    g_vT);

    cudaFuncSetAttribute(gemm_f16k<0, true>,  cudaFuncAttributeMaxDynamicSharedMemorySize, SMEM_BYTES);
    cudaFuncSetAttribute(gemm_f16k<0, false>, cudaFuncAttributeMaxDynamicSharedMemorySize, SMEM_BYTES);
    cudaFuncSetAttribute(gemm_f16k<1, false>, cudaFuncAttributeMaxDynamicSharedMemorySize, SMEM_BYTES);
    cudaFuncSetAttribute(gemm_f16k<2, true>,  cudaFuncAttributeMaxDynamicSharedMemorySize, SMEM_BYTES);

    const float scale = 0.03125f;  // 1/sqrt(1024)
    const int M = BATCH * SEQ;     // 8192

    // x -> half
    {
        size_t n4 = (size_t)M * DIM / 4;
        convert_kernel<<<(unsigned)((n4 + 255) / 256), 256>>>(x, x16, n4);
    }
    // weights: transpose + convert
    transpose_f2h<<<dim3(3 * DIM / 32, DIM / 32, 1), dim3(32, 8)>>>(Wqkv, wqkvT, 3 * DIM, DIM);
    transpose_f2h<<<dim3(DIM / 32, DIM / 32, 1), dim3(32, 8)>>>(Wout, woutT, DIM, DIM);

    // 1) qkv = x @ Wqkv + bqkv  (half out)
    gemm_f16k<0, true><<<dim3(3 * DIM / BN, M / BM, 1), 256, SMEM_BYTES>>>(
        x16, DIM, wqkvT, DIM, qkv, 3 * DIM, DIM,
        bqkv, nullptr, 0.f, 0, 0, 0, 0);

    // V transpose per batch: vT [4][1024][2048]
    transpose_h2h<<<dim3(DIM / 32, SEQ / 32, BATCH), dim3(32, 8)>>>(
        qkv + 2 * DIM, vT, 3 * DIM, SEQ, (long)SEQ * 3 * DIM, (long)DIM * SEQ);

    // 2) scores = Q @ K^T * scale, mask==0 -> 1e-10  (fp32 out)
    gemm_f16k<1, false><<<dim3(SEQ / BN, SEQ / BM, BATCH), 256, SMEM_BYTES>>>(
        qkv, 3 * DIM, qkv + DIM, 3 * DIM, scores, SEQ, DIM,
        nullptr, mask, scale,
        (long)SEQ * 3 * DIM, (long)SEQ * 3 * DIM, (long)SEQ * SEQ, (long)SEQ * SEQ);

    // 3) softmax -> half probs
    softmax_kernel<<<BATCH * SEQ, 256>>>(scores, probs);

    // 4) attn_out = probs @ V  (half out)
    gemm_f16k<2, true><<<dim3(DIM / BN, SEQ / BM, BATCH), 256, SMEM_BYTES>>>(
        probs, SEQ, vT, SEQ, attn, DIM, SEQ,
        nullptr, nullptr, 0.f,
        (long)SEQ * SEQ, (long)DIM * SEQ, (long)SEQ * DIM, 0);

    // 5) out = attn_out @ Wout + bout  (fp32 out)
    gemm_f16k<0, false><<<dim3(DIM / BN, M / BM, 1), 256, SMEM_BYTES>>>(
        attn, DIM, woutT, DIM, out, DIM, DIM,
        bout, nullptr, 0.f, 0, 0, 0, 0);
}

// round 7
// speedup vs baseline: 6.8343x; 1.1023x over previous
#include <cuda_runtime.h>
#include <cuda_fp16.h>
#include <cstdint>

#define BATCH 4
#define SEQ   2048
#define DIM   1024

// ---- scratch (alloc-free rule: __device__ globals) ----
__device__ __half g_x16  [(size_t)BATCH * SEQ * DIM];       // x -> half
__device__ __half g_qkv  [(size_t)BATCH * SEQ * 3 * DIM];   // [8192][3072] half
__device__ float  g_scores[(size_t)BATCH * SEQ * SEQ];      // [4][2048][2048] fp32
__device__ __half g_probs[(size_t)BATCH * SEQ * SEQ];       // softmax(scores) half
__device__ __half g_attn [(size_t)BATCH * SEQ * DIM];       // [8192][1024] half
__device__ __half g_wqkvT[(size_t)3 * DIM * DIM];           // [3072][1024] half
__device__ __half g_woutT[(size_t)DIM * DIM];               // [1024][1024] half
__device__ __half g_vT   [(size_t)BATCH * DIM * SEQ];       // [4][1024][2048] half

// =========================== PTX helpers ===========================
__device__ __forceinline__ void mma_f16(float* d, const uint32_t* a, const uint32_t* b) {
    asm volatile(
        "mma.sync.aligned.m16n8k16.row.col.f32.f16.f16.f32 "
        "{%0,%1,%2,%3}, {%4,%5,%6,%7}, {%8,%9}, {%0,%1,%2,%3};"
        : "+f"(d[0]), "+f"(d[1]), "+f"(d[2]), "+f"(d[3])
        : "r"(a[0]), "r"(a[1]), "r"(a[2]), "r"(a[3]), "r"(b[0]), "r"(b[1]));
}

__device__ __forceinline__ void ldsm_x4(uint32_t* r, uint32_t addr) {
    asm volatile("ldmatrix.sync.aligned.m8n8.x4.shared.b16 {%0,%1,%2,%3}, [%4];"
        : "=r"(r[0]), "=r"(r[1]), "=r"(r[2]), "=r"(r[3]) : "r"(addr));
}

__device__ __forceinline__ uint32_t smem_u32(const void* p) {
    uint32_t a;
    asm("{ .reg .u64 t; cvta.to.shared.u64 t, %1; cvt.u32.u64 %0, t; }"
        : "=r"(a) : "l"(p));
    return a;
}

#define CP_ASYNC16(dst_u32, src_ptr) \
    asm volatile("cp.async.cg.shared.global [%0], [%1], 16;" \
                 :: "r"(dst_u32), "l"(src_ptr) : "memory")
#define CP_COMMIT() asm volatile("cp.async.commit_group;" ::: "memory")
#define CP_WAIT(n)  asm volatile("cp.async.wait_group %0;" :: "n"(n) : "memory")

// =========================== GEMM (mma f16 k16, ldmatrix, BK=64, 2-stage) ====================
// C[M,N] = A[M,K] * B[N,K]^T.  A, B half, K contiguous.
// Block tile 128x128, BK=64. 256 threads = 8 warps (2m x 4n), warp tile 64x32. 2 CTAs/SM.
// MODE 0: +bias[n]   MODE 1: *scale then mask==0 -> 1e-10   MODE 2: plain
// OUTH: write C as half; else fp32.

constexpr int BM = 128, BN = 128, BK = 64;
constexpr int ROW_HALFS = 72;                          // 64 data + 8 pad, 144 B pitch
constexpr int ROW_BYTES = ROW_HALFS * 2;               // 144
constexpr int A_HALFS = BM * ROW_HALFS;                // 9216
constexpr int STAGE_HALFS = 2 * A_HALFS;               // 18432 (A + B)
constexpr int STAGE_BYTES = STAGE_HALFS * 2;           // 36864
constexpr int NSTAGE = 2;
constexpr int SMEM_BYTES = NSTAGE * STAGE_BYTES;       // 73728

template <int MODE, bool OUTH>
__global__ __launch_bounds__(256, 2) void gemm_f16k(
    const __half* __restrict__ A, int lda,
    const __half* __restrict__ B, int ldb,
    void* __restrict__ Cv, int ldc, int K,
    const float* __restrict__ bias,
    const int* __restrict__ mask, float scale,
    long sA, long sB, long sC, long sM)
{
    extern __shared__ __half smem[];
    const uint32_t smem_base = smem_u32(smem);
    const int tid  = threadIdx.x;
    const int lane = tid & 31;
    const int wid  = tid >> 5;
    const int bz   = blockIdx.z;

    A += (long)bz * sA;
    B += (long)bz * sB;
    if (MODE == 1) mask += (long)bz * sM;

    const int m0 = blockIdx.y * BM;
    const int n0 = blockIdx.x * BN;

    const int wm = (wid & 1) * 64;     // warp m offset
    const int wn = (wid >> 1) * 32;    // warp n offset

    // ldmatrix per-lane byte offsets
    const uint32_t a_lane = (uint32_t)((lane & 15) * ROW_BYTES + (lane >> 4) * 16);
    const uint32_t b_lane = (uint32_t)(((lane & 7) + ((lane >> 4) << 3)) * ROW_BYTES
                                       + ((lane >> 3) & 1) * 16);

    const uint32_t a_warp = smem_base + (uint32_t)(wm * ROW_BYTES) + a_lane;
    const uint32_t b_warp = smem_base + (uint32_t)(A_HALFS * 2 + wn * ROW_BYTES) + b_lane;

    // cp.async coords: row = tid>>3 (0..31, +32 stride x4), chunk = (tid&7)*16B of 128B row
    const int lrow = tid >> 3;
    const int lq   = (tid & 7) * 8;    // halfs

    const __half* Aped = A + (size_t)(m0 + lrow) * lda + lq;
    const __half* Bped = B + (size_t)(n0 + lrow) * ldb + lq;
    const uint32_t a_dst0 = smem_base + (uint32_t)(lrow * ROW_BYTES + lq * 2);
    const uint32_t b_dst0 = smem_base + (uint32_t)(A_HALFS * 2 + lrow * ROW_BYTES + lq * 2);

    const int NITER = K / BK;

    auto issue_stage = [&](int stage, int kc) {
        const uint32_t so = (uint32_t)(stage * STAGE_BYTES);
        const int kb = kc * BK;
        #pragma unroll
        for (int i = 0; i < 4; i++)
            CP_ASYNC16(a_dst0 + so + (uint32_t)(i * 32 * ROW_BYTES),
                       Aped + (size_t)(i * 32) * lda + kb);
        #pragma unroll
        for (int i = 0; i < 4; i++)
            CP_ASYNC16(b_dst0 + so + (uint32_t)(i * 32 * ROW_BYTES),
                       Bped + (size_t)(i * 32) * ldb + kb);
    };

    float acc[4][4][4];
    #pragma unroll
    for (int i = 0; i < 4; i++)
        #pragma unroll
        for (int j = 0; j < 4; j++)
            #pragma unroll
            for (int q = 0; q < 4; q++) acc[i][j][q] = 0.f;

    issue_stage(0, 0); CP_COMMIT();

    #pragma unroll 1
    for (int kc = 0; kc < NITER; kc++) {
        CP_WAIT(0);
        __syncthreads();

        if (kc + 1 < NITER) { issue_stage((kc + 1) & 1, kc + 1); CP_COMMIT(); }

        const uint32_t so = (uint32_t)((kc & 1) * STAGE_BYTES);
        const uint32_t a_base = a_warp + so;
        const uint32_t b_base = b_warp + so;

        #pragma unroll
        for (int kk = 0; kk < BK; kk += 16) {
            uint32_t a[4][4], b[4][2];
            #pragma unroll
            for (int mi = 0; mi < 4; mi++)
                ldsm_x4(a[mi], a_base + (uint32_t)(mi * 16 * ROW_BYTES + kk * 2));
            #pragma unroll
            for (int nj = 0; nj < 2; nj++) {
                uint32_t t[4];
                ldsm_x4(t, b_base + (uint32_t)(nj * 16 * ROW_BYTES + kk * 2));
                b[nj * 2 + 0][0] = t[0]; b[nj * 2 + 0][1] = t[1];
                b[nj * 2 + 1][0] = t[2]; b[nj * 2 + 1][1] = t[3];
            }
            #pragma unroll
            for (int mi = 0; mi < 4; mi++)
                #pragma unroll
                for (int ni = 0; ni < 4; ni++)
                    mma_f16(acc[mi][ni], a[mi], b[ni]);
        }
    }

    // ---- epilogue ----
    const int lr = lane >> 2;
    const int lc = lane & 3;
    #pragma unroll
    for (int mi = 0; mi < 4; mi++) {
        #pragma unroll
        for (int half_ = 0; half_ < 2; half_++) {
            const int row = m0 + wm + mi * 16 + lr + half_ * 8;
            const int* mrow = (MODE == 1) ? (mask + (size_t)row * ldc) : nullptr;
            #pragma unroll
            for (int ni = 0; ni < 4; ni++) {
                const int col = n0 + wn + ni * 8 + lc * 2;
                float v0 = acc[mi][ni][half_ * 2 + 0];
                float v1 = acc[mi][ni][half_ * 2 + 1];
                if (MODE == 0) {
                    v0 += bias[col];
                    v1 += bias[col + 1];
                }
                if (MODE == 1) {
                    v0 *= scale; v1 *= scale;
                    const int2 mk = *(const int2*)(mrow + col);
                    if (mk.x == 0) v0 = 1e-10f;
                    if (mk.y == 0) v1 = 1e-10f;
                }
                if (OUTH) {
                    __half* C = (__half*)Cv + (long)bz * sC + (size_t)row * ldc + col;
                    *(__half2*)C = __floats2half2_rn(v0, v1);
                } else {
                    float* C = (float*)Cv + (long)bz * sC + (size_t)row * ldc + col;
                    float2 v; v.x = v0; v.y = v1;
                    *(float2*)C = v;
                }
            }
        }
    }
}

// =========================== convert x: fp32 -> half ===========================
__global__ __launch_bounds__(256) void convert_kernel(
    const float* __restrict__ src, __half* __restrict__ dst, size_t n4)
{
    size_t i = (size_t)blockIdx.x * 256 + threadIdx.x;
    if (i >= n4) return;
    float4 v = ((const float4*)src)[i];
    ((__half2*)dst)[i * 2]     = __floats2half2_rn(v.x, v.y);
    ((__half2*)dst)[i * 2 + 1] = __floats2half2_rn(v.z, v.w);
}

// =========================== transpose fp32 -> half ===========================
__global__ __launch_bounds__(256) void transpose_f2h(
    const float* __restrict__ src, __half* __restrict__ dst,
    int srcLd, int dstLd)
{
    __shared__ float t[32][33];
    const int c0 = blockIdx.x * 32, r0 = blockIdx.y * 32;
    const int tx = threadIdx.x, ty = threadIdx.y;
    #pragma unroll
    for (int i = 0; i < 32; i += 8)
        t[ty + i][tx] = src[(size_t)(r0 + ty + i) * srcLd + c0 + tx];
    __syncthreads();
    #pragma unroll
    for (int i = 0; i < 32; i += 8)
        dst[(size_t)(c0 + ty + i) * dstLd + r0 + tx] = __float2half(t[tx][ty + i]);
}

// =========================== transpose half -> half ===========================
__global__ __launch_bounds__(256) void transpose_h2h(
    const __half* __restrict__ src, __half* __restrict__ dst,
    int srcLd, int dstLd, long sBatch, long dBatch)
{
    __shared__ __half t[32][34];
    src += (long)blockIdx.z * sBatch;
    dst += (long)blockIdx.z * dBatch;
    const int c0 = blockIdx.x * 32, r0 = blockIdx.y * 32;
    const int tx = threadIdx.x, ty = threadIdx.y;
    #pragma unroll
    for (int i = 0; i < 32; i += 8)
        t[ty + i][tx] = src[(size_t)(r0 + ty + i) * srcLd + c0 + tx];
    __syncthreads();
    #pragma unroll
    for (int i = 0; i < 32; i += 8)
        dst[(size_t)(c0 + ty + i) * dstLd + r0 + tx] = t[tx][ty + i];
}

// =========================== softmax: fp32 scores -> half probs ===========================
__global__ __launch_bounds__(256) void softmax_kernel(
    const float* __restrict__ s, __half* __restrict__ o)
{
    const long row = blockIdx.x;
    const float* p = s + row * SEQ;
    __half* q = o + row * SEQ;
    const int tid  = threadIdx.x;
    const int lane = tid & 31;
    const int warp = tid >> 5;

    __shared__ float redm[8];
    __shared__ float reds[8];

    float v[8];
    float m = -1e30f;
    #pragma unroll
    for (int i = 0; i < 8; i++) {
        v[i] = p[tid + i * 256];
        m = fmaxf(m, v[i]);
    }
    #pragma unroll
    for (int oo = 16; oo > 0; oo >>= 1) m = fmaxf(m, __shfl_xor_sync(0xffffffffu, m, oo));
    if (lane == 0) redm[warp] = m;
    __syncthreads();
    float M = redm[0];
    #pragma unroll
    for (int i = 1; i < 8; i++) M = fmaxf(M, redm[i]);

    float sum = 0.f;
    #pragma unroll
    for (int i = 0; i < 8; i++) {
        v[i] = expf(v[i] - M);
        sum += v[i];
    }
    #pragma unroll
    for (int oo = 16; oo > 0; oo >>= 1) sum += __shfl_xor_sync(0xffffffffu, sum, oo);
    if (lane == 0) reds[warp] = sum;
    __syncthreads();
    float total = 0.f;
    #pragma unroll
    for (int i = 0; i < 8; i++) total += reds[i];

    const float inv = 1.0f / total;
    #pragma unroll
    for (int i = 0; i < 8; i++) q[tid + i * 256] = __float2half(v[i] * inv);
}

// =========================== launch ===========================
extern "C" void kernel_launch(void* const* d_in, const int* in_sizes, int n_in,
                              void* d_out, int out_size)
{
    const float* x    = (const float*)d_in[0];
    const int*   mask = (const int*)  d_in[1];
    const float* Wqkv = (const float*)d_in[2];
    const float* bqkv = (const float*)d_in[3];
    const float* Wout = (const float*)d_in[4];
    const float* bout = (const float*)d_in[5];
    float* out = (float*)d_out;

    __half* x16;   cudaGetSymbolAddress((void**)&x16,   g_x16);
    __half* qkv;   cudaGetSymbolAddress((void**)&qkv,   g_qkv);
    float*  scores;cudaGetSymbolAddress((void**)&scores,g_scores);
    __half* probs; cudaGetSymbolAddress((void**)&probs, g_probs);
    __half* attn;  cudaGetSymbolAddress((void**)&attn,  g_attn);
    __half* wqkvT; cudaGetSymbolAddress((void**)&wqkvT, g_wqkvT);
    __half* woutT; cudaGetSymbolAddress((void**)&woutT, g_woutT);
    __half* vT;    cudaGetSymbolAddress((void**)&vT,    g_vT);

    cudaFuncSetAttribute(gemm_f16k<0, true>,  cudaFuncAttributeMaxDynamicSharedMemorySize, SMEM_BYTES);
    cudaFuncSetAttribute(gemm_f16k<0, false>, cudaFuncAttributeMaxDynamicSharedMemorySize, SMEM_BYTES);
    cudaFuncSetAttribute(gemm_f16k<1, false>, cudaFuncAttributeMaxDynamicSharedMemorySize, SMEM_BYTES);
    cudaFuncSetAttribute(gemm_f16k<2, true>,  cudaFuncAttributeMaxDynamicSharedMemorySize, SMEM_BYTES);

    const float scale = 0.03125f;  // 1/sqrt(1024)
    const int M = BATCH * SEQ;     // 8192

    // x -> half
    {
        size_t n4 = (size_t)M * DIM / 4;
        convert_kernel<<<(unsigned)((n4 + 255) / 256), 256>>>(x, x16, n4);
    }
    // weights: transpose + convert
    transpose_f2h<<<dim3(3 * DIM / 32, DIM / 32, 1), dim3(32, 8)>>>(Wqkv, wqkvT, 3 * DIM, DIM);
    transpose_f2h<<<dim3(DIM / 32, DIM / 32, 1), dim3(32, 8)>>>(Wout, woutT, DIM, DIM);

    // 1) qkv = x @ Wqkv + bqkv  (half out)
    gemm_f16k<0, true><<<dim3(3 * DIM / BN, M / BM, 1), 256, SMEM_BYTES>>>(
        x16, DIM, wqkvT, DIM, qkv, 3 * DIM, DIM,
        bqkv, nullptr, 0.f, 0, 0, 0, 0);

    // V transpose per batch: vT [4][1024][2048]
    transpose_h2h<<<dim3(DIM / 32, SEQ / 32, BATCH), dim3(32, 8)>>>(
        qkv + 2 * DIM, vT, 3 * DIM, SEQ, (long)SEQ * 3 * DIM, (long)DIM * SEQ);

    // 2) scores = Q @ K^T * scale, mask==0 -> 1e-10  (fp32 out)
    gemm_f16k<1, false><<<dim3(SEQ / BN, SEQ / BM, BATCH), 256, SMEM_BYTES>>>(
        qkv, 3 * DIM, qkv + DIM, 3 * DIM, scores, SEQ, DIM,
        nullptr, mask, scale,
        (long)SEQ * 3 * DIM, (long)SEQ * 3 * DIM, (long)SEQ * SEQ, (long)SEQ * SEQ);

    // 3) softmax -> half probs
    softmax_kernel<<<BATCH * SEQ, 256>>>(scores, probs);

    // 4) attn_out = probs @ V  (half out)
    gemm_f16k<2, true><<<dim3(DIM / BN, SEQ / BM, BATCH), 256, SMEM_BYTES>>>(
        probs, SEQ, vT, SEQ, attn, DIM, SEQ,
        nullptr, nullptr, 0.f,
        (long)SEQ * SEQ, (long)DIM * SEQ, (long)SEQ * DIM, 0);

    // 5) out = attn_out @ Wout + bout  (fp32 out)
    gemm_f16k<0, false><<<dim3(DIM / BN, M / BM, 1), 256, SMEM_BYTES>>>(
        attn, DIM, woutT, DIM, out, DIM, DIM,
        bout, nullptr, 0.f, 0, 0, 0, 0);
}